// round 16
// baseline (speedup 1.0000x reference)
#include <cuda_runtime.h>
#include <cuda_bf16.h>
#include <cuda_fp16.h>
#include <cstdint>
#include <stdint.h>
#include <math.h>

#define NP 100000
#define NA 100000
#define DIN 256
#define DOUT 128
#define NE 1600000
#define SLOPE 0.2f
#define CAP 96

// ---------------- scratch (static device globals; allocation-free) ----------
__device__ __align__(16) float g_Wh_P[NP * DOUT];
__device__ __align__(16) float g_Wh_A[NA * DOUT];
__device__ __align__(16) __half g_m_p2p[NP * DOUT];
__device__ __align__(16) __half g_m_p2a[NP * DOUT];
__device__ __align__(16) __half g_m_a2p[NA * DOUT];
__device__ __align__(16) __half g_m_a2a[NA * DOUT];
__device__ float g_s_p2p_src[NP];
__device__ float g_s_p2p_dst[NP];
__device__ float g_s_p2a_src[NP];
__device__ float g_s_p2a_dst[NA];
__device__ float g_s_a2p_src[NA];
__device__ float g_s_a2p_dst[NP];
__device__ float g_s_a2a_src[NA];
__device__ float g_s_a2a_dst[NA];
__device__ __align__(16) int2 g_bkt[4][NP * CAP];
__device__ int g_cnt[4][NP];
// transposed/split weights: [6 matrices][128 N][256 K] bf16
__device__ __align__(16) __nv_bfloat16 g_Bhi[6 * 128 * 256];
__device__ __align__(16) __nv_bfloat16 g_Blo[6 * 128 * 256];

// ---------------- PTX helpers (baseline sm_103, NO 'a' features) ------------
__device__ __forceinline__ uint32_t smem_u32(const void* p) {
    uint32_t a;
    asm("{ .reg .u64 t; cvta.to.shared.u64 t, %1; cvt.u32.u64 %0, t; }"
        : "=r"(a) : "l"(p));
    return a;
}
__device__ __forceinline__ void ldsm_x4(uint32_t a[4], uint32_t addr) {
    asm volatile("ldmatrix.sync.aligned.m8n8.x4.shared.b16 {%0,%1,%2,%3}, [%4];"
                 : "=r"(a[0]), "=r"(a[1]), "=r"(a[2]), "=r"(a[3]) : "r"(addr));
}
__device__ __forceinline__ void mma_bf16(float c[4], const uint32_t a[4],
                                         const uint32_t b[2]) {
    asm volatile(
        "mma.sync.aligned.m16n8k16.row.col.f32.bf16.bf16.f32 "
        "{%0,%1,%2,%3}, {%4,%5,%6,%7}, {%8,%9}, {%0,%1,%2,%3};"
        : "+f"(c[0]), "+f"(c[1]), "+f"(c[2]), "+f"(c[3])
        : "r"(a[0]), "r"(a[1]), "r"(a[2]), "r"(a[3]), "r"(b[0]), "r"(b[1]));
}
__device__ __forceinline__ void cp16(uint32_t saddr, const void* g) {
    asm volatile("cp.async.cg.shared.global [%0], [%1], 16;"
                 :: "r"(saddr), "l"(g));
}
#define CP_COMMIT() asm volatile("cp.async.commit_group;" ::: "memory")
#define CP_WAIT0()  asm volatile("cp.async.wait_group 0;" ::: "memory")
#define CP_WAIT1()  asm volatile("cp.async.wait_group 1;" ::: "memory")

// ---------------- weight prep: W[k][n] -> B[w][n][k] hi/lo bf16 -------------
__global__ void prep_w_kernel(const float* __restrict__ W0, const float* __restrict__ W1,
                              const float* __restrict__ W2, const float* __restrict__ W3,
                              const float* __restrict__ W4, const float* __restrict__ W5,
                              __nv_bfloat16* __restrict__ bhi,
                              __nv_bfloat16* __restrict__ blo)
{
    int i = blockIdx.x * blockDim.x + threadIdx.x;
    if (i >= 6 * 128 * 256) return;
    int w = i >> 15;
    int rem = i & 32767;
    int nrow = rem >> 8;
    int k = rem & 255;
    const float* W = (w == 0) ? W0 : (w == 1) ? W1 : (w == 2) ? W2
                   : (w == 3) ? W3 : (w == 4) ? W4 : W5;
    float v = W[k * 128 + nrow];
    __nv_bfloat16 h = __float2bfloat16(v);
    __nv_bfloat16 l = __float2bfloat16(v - __bfloat162float(h));
    bhi[i] = h;
    blo[i] = l;
}

// ---------------- HMMA GEMM: cp.async fp32-staged A + cp.async B ------------
#define ASTR 72
#define KCH 64
#define SM_AHI 0
#define SM_ALO 18432
#define SM_STG 36864
#define SM_B   69632
#define GEMM_SMEM 106496

__device__ __forceinline__ void split1(float x, __nv_bfloat16& h, __nv_bfloat16& l) {
    h = __float2bfloat16(x);
    l = __float2bfloat16(x - __bfloat162float(h));
}

struct GemmArgs {
    const float* feat;
    const __nv_bfloat16* Bhi;
    const __nv_bfloat16* Blo;
    const float *b0, *b1, *b2;
    const float *aD1, *aD2, *aS1, *aS2;
    float* o0;
    __half *o1h, *o2h;
    float *sD1, *sD2, *sS1, *sS2;
    int n;
};

__global__ __launch_bounds__(256, 2)
void gemm_mma_kernel(GemmArgs GP, GemmArgs GA)
{
    extern __shared__ __align__(16) char smem[];
    __shared__ float sacc[2][128];
    const uint32_t sbase = smem_u32(smem);

    const GemmArgs& G = blockIdx.z ? GA : GP;
    const int w    = blockIdx.x;
    const int row0 = blockIdx.y * 128;
    const int tid  = threadIdx.x;
    const int warp = tid >> 5;
    const int lane = tid & 31;
    const int n    = G.n;
    const float* feat = G.feat;

    const __nv_bfloat16* Bh = G.Bhi + (size_t)w * 128 * 256;
    const __nv_bfloat16* Bl = G.Blo + (size_t)w * 128 * 256;

    const int m_base = (warp >> 2) * 64;
    const int n_base = (warp & 3) * 32;

    float c[4][4][4];
#pragma unroll
    for (int mt = 0; mt < 4; mt++)
#pragma unroll
        for (int nt = 0; nt < 4; nt++)
#pragma unroll
            for (int r = 0; r < 4; r++) c[mt][nt][r] = 0.f;

    uint32_t aRow[4], bRow4[2];
#pragma unroll
    for (int mt = 0; mt < 4; mt++) {
        int r = m_base + mt * 16 + (lane & 15);
        aRow[mt] = (uint32_t)(r * ASTR * 2) + (((uint32_t)lane >> 4) << 4);
    }
#pragma unroll
    for (int np = 0; np < 2; np++) {
        int r = n_base + np * 16 + (((int)lane >> 4) << 3) + (lane & 7);
        bRow4[np] = (uint32_t)(r * ASTR * 2) + ((((uint32_t)lane >> 3) & 1) << 4);
    }

    if (tid < 256) sacc[tid >> 7][tid & 127] = 0.f;

    const int b_nr  = tid >> 3;
    const int b_c16 = tid & 7;

    auto issue_B = [&](int kc) {
#pragma unroll
        for (int it = 0; it < 4; it++) {
            int nr = b_nr + it * 32;
            uint32_t off = (uint32_t)((nr * ASTR + b_c16 * 8) * 2);
            cp16(sbase + SM_B + off, Bh + (size_t)nr * DIN + kc + b_c16 * 8);
            cp16(sbase + SM_B + 18432 + off, Bl + (size_t)nr * DIN + kc + b_c16 * 8);
        }
        CP_COMMIT();
    };
    auto issue_STG = [&](int kc) {
#pragma unroll
        for (int it = 0; it < 8; it++) {
            int idx = it * 256 + tid;
            int r   = idx >> 4;
            int c4  = idx & 15;
            if (row0 + r < n)
                cp16(sbase + SM_STG + (uint32_t)(r * 256 + c4 * 16),
                     feat + (size_t)(row0 + r) * DIN + kc + c4 * 4);
        }
        CP_COMMIT();
    };
    auto cvt_STG = [&]() {
#pragma unroll
        for (int it = 0; it < 8; it++) {
            int idx = it * 256 + tid;
            int r   = idx >> 4;
            int c4  = idx & 15;
            float4 v = (row0 + r < n)
                ? *(const float4*)(smem + SM_STG + r * 256 + c4 * 16)
                : make_float4(0.f, 0.f, 0.f, 0.f);
            __nv_bfloat16 h0, l0, h1, l1, h2, l2, h3, l3;
            split1(v.x, h0, l0); split1(v.y, h1, l1);
            split1(v.z, h2, l2); split1(v.w, h3, l3);
            __nv_bfloat162 hA = __halves2bfloat162(h0, h1);
            __nv_bfloat162 hB = __halves2bfloat162(h2, h3);
            __nv_bfloat162 lA = __halves2bfloat162(l0, l1);
            __nv_bfloat162 lB = __halves2bfloat162(l2, l3);
            uint32_t off = (uint32_t)((r * ASTR + c4 * 4) * 2);
            *(uint2*)(smem + SM_AHI + off) =
                make_uint2(*(uint32_t*)&hA, *(uint32_t*)&hB);
            *(uint2*)(smem + SM_ALO + off) =
                make_uint2(*(uint32_t*)&lA, *(uint32_t*)&lB);
        }
    };

    // prologue
    issue_STG(0);
    issue_B(0);
    CP_WAIT0();
    __syncthreads();
    cvt_STG();
    issue_STG(KCH);
    __syncthreads();

    // mainloop
#pragma unroll
    for (int cidx = 0; cidx < 4; cidx++) {
#pragma unroll
        for (int ks = 0; ks < 4; ks++) {
            const uint32_t kofs = (uint32_t)(ks * 32);
            uint32_t bh[4][2], bl[4][2];
#pragma unroll
            for (int np = 0; np < 2; np++) {
                uint32_t t4[4];
                ldsm_x4(t4, sbase + SM_B + bRow4[np] + kofs);
                bh[2 * np][0] = t4[0]; bh[2 * np][1] = t4[1];
                bh[2 * np + 1][0] = t4[2]; bh[2 * np + 1][1] = t4[3];
                ldsm_x4(t4, sbase + SM_B + 18432 + bRow4[np] + kofs);
                bl[2 * np][0] = t4[0]; bl[2 * np][1] = t4[1];
                bl[2 * np + 1][0] = t4[2]; bl[2 * np + 1][1] = t4[3];
            }
#pragma unroll
            for (int mt = 0; mt < 4; mt++) {
                uint32_t ah[4], al[4];
                ldsm_x4(ah, sbase + SM_AHI + aRow[mt] + kofs);
                ldsm_x4(al, sbase + SM_ALO + aRow[mt] + kofs);
#pragma unroll
                for (int nt = 0; nt < 4; nt++) {
                    mma_bf16(c[mt][nt], ah, bh[nt]);
                    mma_bf16(c[mt][nt], al, bh[nt]);
                    mma_bf16(c[mt][nt], ah, bl[nt]);
                }
            }
        }
        __syncthreads();
        if (cidx < 3) {
            issue_B((cidx + 1) * KCH);
            CP_WAIT1();
            cvt_STG();
            if (cidx + 2 <= 3) {
                issue_STG((cidx + 2) * KCH);
                CP_WAIT1();
            } else {
                CP_WAIT0();
            }
            __syncthreads();
        }
    }

    // epilogue: bias + store + fused s-dots
    const float* bw = (w == 0) ? G.b0 : (w == 1) ? G.b1 : G.b2;
    const float* aq1 = (w == 0) ? G.aD1 : (w == 1) ? G.aS1 : G.aS2;
    const int lr = lane >> 2;
    const int lc = (lane & 3) * 2;
    float2 bv[4], a1v[4], a2v[4];
#pragma unroll
    for (int nt = 0; nt < 4; nt++) {
        int col = n_base + nt * 8 + lc;
        bv[nt]  = *(const float2*)(bw + col);
        a1v[nt] = *(const float2*)(aq1 + col);
        a2v[nt] = (w == 0) ? *(const float2*)(G.aD2 + col) : make_float2(0.f, 0.f);
    }

#pragma unroll
    for (int mt = 0; mt < 4; mt++) {
        int r1 = row0 + m_base + mt * 16 + lr;
        int r2 = r1 + 8;
        float pa1 = 0.f, pa2 = 0.f, pb1 = 0.f, pb2 = 0.f;
#pragma unroll
        for (int nt = 0; nt < 4; nt++) {
            int col = n_base + nt * 8 + lc;
            float v0 = c[mt][nt][0] + bv[nt].x;
            float v1 = c[mt][nt][1] + bv[nt].y;
            float v2 = c[mt][nt][2] + bv[nt].x;
            float v3 = c[mt][nt][3] + bv[nt].y;
            if (w == 0) {
                if (r1 < n) *(float2*)(G.o0 + (size_t)r1 * DOUT + col) = make_float2(v0, v1);
                if (r2 < n) *(float2*)(G.o0 + (size_t)r2 * DOUT + col) = make_float2(v2, v3);
            } else {
                __half* oh = (w == 1) ? G.o1h : G.o2h;
                if (r1 < n) *(__half2*)(oh + (size_t)r1 * DOUT + col) = __floats2half2_rn(v0, v1);
                if (r2 < n) *(__half2*)(oh + (size_t)r2 * DOUT + col) = __floats2half2_rn(v2, v3);
            }
            pa1 += v0 * a1v[nt].x + v1 * a1v[nt].y;
            pa2 += v2 * a1v[nt].x + v3 * a1v[nt].y;
            if (w == 0) {
                pb1 += v0 * a2v[nt].x + v1 * a2v[nt].y;
                pb2 += v2 * a2v[nt].x + v3 * a2v[nt].y;
            }
        }
        pa1 += __shfl_xor_sync(0xffffffffu, pa1, 1);
        pa1 += __shfl_xor_sync(0xffffffffu, pa1, 2);
        pa2 += __shfl_xor_sync(0xffffffffu, pa2, 1);
        pa2 += __shfl_xor_sync(0xffffffffu, pa2, 2);
        pb1 += __shfl_xor_sync(0xffffffffu, pb1, 1);
        pb1 += __shfl_xor_sync(0xffffffffu, pb1, 2);
        pb2 += __shfl_xor_sync(0xffffffffu, pb2, 1);
        pb2 += __shfl_xor_sync(0xffffffffu, pb2, 2);
        if ((lane & 3) == 0) {
            int lrow = m_base + mt * 16 + lr;
            atomicAdd(&sacc[0][lrow], pa1);
            atomicAdd(&sacc[0][lrow + 8], pa2);
            if (w == 0) {
                atomicAdd(&sacc[1][lrow], pb1);
                atomicAdd(&sacc[1][lrow + 8], pb2);
            }
        }
    }
    __syncthreads();
    if (tid < 128 && row0 + tid < n) {
        if (w == 0) {
            G.sD1[row0 + tid] = sacc[0][tid];
            G.sD2[row0 + tid] = sacc[1][tid];
        } else if (w == 1) {
            G.sS1[row0 + tid] = sacc[0][tid];
        } else {
            G.sS2[row0 + tid] = sacc[0][tid];
        }
    }
}

// ---------------- edge pipeline ---------------------------------------------
struct EdgeParams {
    const int*   src[4];
    const int*   dst[4];
    const float* ssrc[4];
    int2*        bkt[4];
    int*         cnt[4];
};

__global__ void zero_cnt_kernel(int* __restrict__ cnt)
{
    int i = blockIdx.x * blockDim.x + threadIdx.x;
    if (i < 4 * NP) cnt[i] = 0;
}

#define SC_UNROLL 4
__global__ void scatter4_kernel(EdgeParams P)
{
    const int t = blockIdx.y;
    const int base = blockIdx.x * blockDim.x * SC_UNROLL + threadIdx.x;
    const int* __restrict__ srcp = P.src[t];
    const int* __restrict__ dstp = P.dst[t];
    const float* __restrict__ sp = P.ssrc[t];
    int*  __restrict__ cntp = P.cnt[t];
    int2* __restrict__ bktp = P.bkt[t];

    int  s[SC_UNROLL], d[SC_UNROLL];
    bool ok[SC_UNROLL];
#pragma unroll
    for (int u = 0; u < SC_UNROLL; u++) {
        int i = base + u * 256;
        ok[u] = (i < NE);
        s[u] = ok[u] ? srcp[i] : 0;
        d[u] = ok[u] ? dstp[i] : 0;
    }
    float es[SC_UNROLL];
#pragma unroll
    for (int u = 0; u < SC_UNROLL; u++)
        es[u] = __ldg(&sp[s[u]]);
#pragma unroll
    for (int u = 0; u < SC_UNROLL; u++) {
        if (!ok[u]) continue;
        int pos = atomicAdd(&cntp[d[u]], 1);
        if (pos < CAP)
            __stcs(&bktp[(size_t)d[u] * CAP + pos],
                   make_int2(s[u], __float_as_int(es[u])));
    }
}

// softmax-weighted gather, 4x-unrolled MLP. NO max pass: scores are sums of
// two N(0,~0.8) dots -> |e| <~ 5 over all 6.4M edges, exp() safe; softmax is
// shift-invariant so dropping the max shift is mathematically identical.
__device__ __forceinline__ float4 gat_one(const int* __restrict__ cnt,
                                          const int2* __restrict__ bkt,
                                          const __half* __restrict__ msg,
                                          float sd, int node, int lane)
{
    int c = cnt[node];
    if (c > CAP) c = CAP;
    float4 acc = make_float4(0.f, 0.f, 0.f, 0.f);
    if (c == 0) return acc;
    const int2* bp = bkt + (size_t)node * CAP;

    float dsum = 0.f;
    for (int j = lane; j < c; j += 32) {
        float ev = __int_as_float(bp[j].y) + sd;
        ev = ev > 0.f ? ev : SLOPE * ev;
        dsum += __expf(ev);
    }
#pragma unroll
    for (int o = 16; o > 0; o >>= 1)
        dsum += __shfl_xor_sync(0xffffffffu, dsum, o);
    float inv = 1.f / dsum;

    const uint32_t loff = (uint32_t)lane * 4;
    int j = 0;
    for (; j + 4 <= c; j += 4) {
        int2 b0 = bp[j], b1 = bp[j + 1], b2 = bp[j + 2], b3 = bp[j + 3];
        uint2 r0 = *(const uint2*)(msg + (size_t)b0.x * DOUT + loff);
        uint2 r1 = *(const uint2*)(msg + (size_t)b1.x * DOUT + loff);
        uint2 r2 = *(const uint2*)(msg + (size_t)b2.x * DOUT + loff);
        uint2 r3 = *(const uint2*)(msg + (size_t)b3.x * DOUT + loff);
        float e0 = __int_as_float(b0.y) + sd; e0 = e0 > 0.f ? e0 : SLOPE * e0;
        float e1 = __int_as_float(b1.y) + sd; e1 = e1 > 0.f ? e1 : SLOPE * e1;
        float e2 = __int_as_float(b2.y) + sd; e2 = e2 > 0.f ? e2 : SLOPE * e2;
        float e3 = __int_as_float(b3.y) + sd; e3 = e3 > 0.f ? e3 : SLOPE * e3;
        float w0 = __expf(e0), w1 = __expf(e1);
        float w2 = __expf(e2), w3 = __expf(e3);
        float2 f;
        f = __half22float2(*(__half2*)&r0.x); acc.x += w0 * f.x; acc.y += w0 * f.y;
        f = __half22float2(*(__half2*)&r0.y); acc.z += w0 * f.x; acc.w += w0 * f.y;
        f = __half22float2(*(__half2*)&r1.x); acc.x += w1 * f.x; acc.y += w1 * f.y;
        f = __half22float2(*(__half2*)&r1.y); acc.z += w1 * f.x; acc.w += w1 * f.y;
        f = __half22float2(*(__half2*)&r2.x); acc.x += w2 * f.x; acc.y += w2 * f.y;
        f = __half22float2(*(__half2*)&r2.y); acc.z += w2 * f.x; acc.w += w2 * f.y;
        f = __half22float2(*(__half2*)&r3.x); acc.x += w3 * f.x; acc.y += w3 * f.y;
        f = __half22float2(*(__half2*)&r3.y); acc.z += w3 * f.x; acc.w += w3 * f.y;
    }
    for (; j < c; j++) {
        int2 b = bp[j];
        float ev = __int_as_float(b.y) + sd;
        ev = ev > 0.f ? ev : SLOPE * ev;
        float w = __expf(ev);
        uint2 raw = *(const uint2*)(msg + (size_t)b.x * DOUT + loff);
        float2 f01 = __half22float2(*(__half2*)&raw.x);
        float2 f23 = __half22float2(*(__half2*)&raw.y);
        acc.x += w * f01.x;
        acc.y += w * f01.y;
        acc.z += w * f23.x;
        acc.w += w * f23.y;
    }
    acc.x *= inv; acc.y *= inv; acc.z *= inv; acc.w *= inv;
    return acc;
}

__global__ void gather_combine_kernel(
    const int* __restrict__ cnt0, const int2* __restrict__ bkt0,
    const __half* __restrict__ msg0, const float* __restrict__ sdst0,
    const int* __restrict__ cnt1, const int2* __restrict__ bkt1,
    const __half* __restrict__ msg1, const float* __restrict__ sdst1,
    const float* __restrict__ Wh, float* __restrict__ out, int n)
{
    int node = (blockIdx.x * blockDim.x + threadIdx.x) >> 5;
    int lane = threadIdx.x & 31;
    if (node >= n) return;

    float sd0 = __ldg(&sdst0[node]);
    float sd1 = __ldg(&sdst1[node]);
    float4 r0 = gat_one(cnt0, bkt0, msg0, sd0, node, lane);
    float4 r1 = gat_one(cnt1, bkt1, msg1, sd1, node, lane);
    float4 v  = *(const float4*)(Wh + (size_t)node * DOUT + lane * 4);
    v.x = fmaxf(v.x + r0.x + r1.x, 0.f);
    v.y = fmaxf(v.y + r0.y + r1.y, 0.f);
    v.z = fmaxf(v.z + r0.z + r1.z, 0.f);
    v.w = fmaxf(v.w + r0.w + r1.w, 0.f);
    *(float4*)(out + (size_t)node * DOUT + lane * 4) = v;
}

// ---------------- launch ----------------------------------------------------
static void* sym_addr(const void* sym)
{
    void* p = nullptr;
    cudaGetSymbolAddress(&p, sym);
    return p;
}

extern "C" void kernel_launch(void* const* d_in, const int* in_sizes, int n_in,
                              void* d_out, int out_size)
{
    const float* feat_P  = (const float*)d_in[0];
    const float* feat_A  = (const float*)d_in[1];
    const int*   p2p_src = (const int*)d_in[2];
    const int*   p2p_dst = (const int*)d_in[3];
    const int*   p2a_src = (const int*)d_in[4];
    const int*   p2a_dst = (const int*)d_in[5];
    const int*   a2p_src = (const int*)d_in[6];
    const int*   a2p_dst = (const int*)d_in[7];
    const int*   a2a_src = (const int*)d_in[8];
    const int*   a2a_dst = (const int*)d_in[9];
    const float* W_P   = (const float*)d_in[10];
    const float* b_P   = (const float*)d_in[11];
    const float* W_A   = (const float*)d_in[12];
    const float* b_A   = (const float*)d_in[13];
    const float* W_p2p = (const float*)d_in[14];
    const float* b_p2p = (const float*)d_in[15];
    const float* W_p2a = (const float*)d_in[16];
    const float* b_p2a = (const float*)d_in[17];
    const float* W_a2p = (const float*)d_in[18];
    const float* b_a2p = (const float*)d_in[19];
    const float* W_a2a = (const float*)d_in[20];
    const float* b_a2a = (const float*)d_in[21];
    const float* a_p2p = (const float*)d_in[22];
    const float* a_p2a = (const float*)d_in[23];
    const float* a_a2p = (const float*)d_in[24];
    const float* a_a2a = (const float*)d_in[25];

    float* Wh_P  = (float*)sym_addr(g_Wh_P);
    float* Wh_A  = (float*)sym_addr(g_Wh_A);
    __half* m_p2p = (__half*)sym_addr(g_m_p2p);
    __half* m_p2a = (__half*)sym_addr(g_m_p2a);
    __half* m_a2p = (__half*)sym_addr(g_m_a2p);
    __half* m_a2a = (__half*)sym_addr(g_m_a2a);
    float* s_p2p_src = (float*)sym_addr(g_s_p2p_src);
    float* s_p2p_dst = (float*)sym_addr(g_s_p2p_dst);
    float* s_p2a_src = (float*)sym_addr(g_s_p2a_src);
    float* s_p2a_dst = (float*)sym_addr(g_s_p2a_dst);
    float* s_a2p_src = (float*)sym_addr(g_s_a2p_src);
    float* s_a2p_dst = (float*)sym_addr(g_s_a2p_dst);
    float* s_a2a_src = (float*)sym_addr(g_s_a2a_src);
    float* s_a2a_dst = (float*)sym_addr(g_s_a2a_dst);
    int2* bkt = (int2*)sym_addr(g_bkt);
    int*  cnt = (int*)sym_addr(g_cnt);
    __nv_bfloat16* Bhi = (__nv_bfloat16*)sym_addr(g_Bhi);
    __nv_bfloat16* Blo = (__nv_bfloat16*)sym_addr(g_Blo);

    float* out = (float*)d_out;

    // 0) weight transpose + bf16 split; zero counters
    prep_w_kernel<<<(6 * 128 * 256 + 255) / 256, 256>>>(
        W_P, W_p2p, W_p2a, W_A, W_a2p, W_a2a, Bhi, Blo);
    zero_cnt_kernel<<<(4 * NP + 255) / 256, 256>>>(cnt);

    // 1) merged HMMA GEMM launch (both families; z selects)
    cudaFuncSetAttribute(gemm_mma_kernel,
                         cudaFuncAttributeMaxDynamicSharedMemorySize, GEMM_SMEM);
    {
        GemmArgs GP, GA;
        GP.feat = feat_P; GP.n = NP;
        GP.Bhi = Bhi; GP.Blo = Blo;
        GP.b0 = b_P; GP.b1 = b_p2p; GP.b2 = b_p2a;
        GP.aD1 = a_p2p + DOUT; GP.aD2 = a_a2p + DOUT;
        GP.aS1 = a_p2p; GP.aS2 = a_p2a;
        GP.o0 = Wh_P; GP.o1h = m_p2p; GP.o2h = m_p2a;
        GP.sD1 = s_p2p_dst; GP.sD2 = s_a2p_dst;
        GP.sS1 = s_p2p_src; GP.sS2 = s_p2a_src;

        GA.feat = feat_A; GA.n = NA;
        GA.Bhi = Bhi + 3 * 128 * 256; GA.Blo = Blo + 3 * 128 * 256;
        GA.b0 = b_A; GA.b1 = b_a2p; GA.b2 = b_a2a;
        GA.aD1 = a_p2a + DOUT; GA.aD2 = a_a2a + DOUT;
        GA.aS1 = a_a2p; GA.aS2 = a_a2a;
        GA.o0 = Wh_A; GA.o1h = m_a2p; GA.o2h = m_a2a;
        GA.sD1 = s_p2a_dst; GA.sD2 = s_a2a_dst;
        GA.sS1 = s_a2p_src; GA.sS2 = s_a2a_src;

        dim3 grid(3, (NP + 127) / 128, 2);
        gemm_mma_kernel<<<grid, 256, GEMM_SMEM>>>(GP, GA);
    }

    // 2) scatter (4 types; 4 edges/thread for MLP)
    EdgeParams EP;
    EP.src[0] = p2p_src; EP.dst[0] = p2p_dst; EP.ssrc[0] = s_p2p_src;
    EP.src[1] = a2p_src; EP.dst[1] = a2p_dst; EP.ssrc[1] = s_a2p_src;
    EP.src[2] = p2a_src; EP.dst[2] = p2a_dst; EP.ssrc[2] = s_p2a_src;
    EP.src[3] = a2a_src; EP.dst[3] = a2a_dst; EP.ssrc[3] = s_a2a_src;
    for (int t = 0; t < 4; t++) {
        EP.bkt[t] = bkt + (size_t)t * NP * CAP;
        EP.cnt[t] = cnt + (size_t)t * NP;
    }
    {
        dim3 gs((NE + 256 * SC_UNROLL - 1) / (256 * SC_UNROLL), 4);
        scatter4_kernel<<<gs, 256>>>(EP);
    }

    // 3) fused gather + combine + ReLU (two launches, as in R12)
    {
        int grid = (NP * 32 + 255) / 256;
        gather_combine_kernel<<<grid, 256>>>(
            EP.cnt[0], EP.bkt[0], m_p2p, s_p2p_dst,
            EP.cnt[1], EP.bkt[1], m_a2p, s_a2p_dst,
            Wh_P, out, NP);
        gather_combine_kernel<<<grid, 256>>>(
            EP.cnt[2], EP.bkt[2], m_p2a, s_p2a_dst,
            EP.cnt[3], EP.bkt[3], m_a2a, s_a2a_dst,
            Wh_A, out + (size_t)NP * DOUT, NA);
    }
}

// round 17
// speedup vs baseline: 1.1154x; 1.1154x over previous
#include <cuda_runtime.h>
#include <cuda_bf16.h>
#include <cuda_fp16.h>
#include <cstdint>
#include <stdint.h>
#include <math.h>

#define NP 100000
#define NA 100000
#define DIN 256
#define DOUT 128
#define NE 1600000
#define SLOPE 0.2f
#define CAP 96

// ---------------- scratch (static device globals; allocation-free) ----------
__device__ __align__(16) float g_Wh_P[NP * DOUT];
__device__ __align__(16) float g_Wh_A[NA * DOUT];
__device__ __align__(16) __half g_m_p2p[NP * DOUT];
__device__ __align__(16) __half g_m_p2a[NP * DOUT];
__device__ __align__(16) __half g_m_a2p[NA * DOUT];
__device__ __align__(16) __half g_m_a2a[NA * DOUT];
__device__ float g_s_p2p_src[NP];
__device__ float g_s_p2p_dst[NP];
__device__ float g_s_p2a_src[NP];
__device__ float g_s_p2a_dst[NA];
__device__ float g_s_a2p_src[NA];
__device__ float g_s_a2p_dst[NP];
__device__ float g_s_a2a_src[NA];
__device__ float g_s_a2a_dst[NA];
__device__ __align__(16) int2 g_bkt[4][NP * CAP];
__device__ int g_cnt[4][NP];
// transposed/split weights: [6 matrices][128 N][256 K] bf16
__device__ __align__(16) __nv_bfloat16 g_Bhi[6 * 128 * 256];
__device__ __align__(16) __nv_bfloat16 g_Blo[6 * 128 * 256];

// ---------------- PTX helpers (baseline sm_103, NO 'a' features) ------------
__device__ __forceinline__ uint32_t smem_u32(const void* p) {
    uint32_t a;
    asm("{ .reg .u64 t; cvta.to.shared.u64 t, %1; cvt.u32.u64 %0, t; }"
        : "=r"(a) : "l"(p));
    return a;
}
__device__ __forceinline__ void ldsm_x4(uint32_t a[4], uint32_t addr) {
    asm volatile("ldmatrix.sync.aligned.m8n8.x4.shared.b16 {%0,%1,%2,%3}, [%4];"
                 : "=r"(a[0]), "=r"(a[1]), "=r"(a[2]), "=r"(a[3]) : "r"(addr));
}
__device__ __forceinline__ void mma_bf16(float c[4], const uint32_t a[4],
                                         const uint32_t b[2]) {
    asm volatile(
        "mma.sync.aligned.m16n8k16.row.col.f32.bf16.bf16.f32 "
        "{%0,%1,%2,%3}, {%4,%5,%6,%7}, {%8,%9}, {%0,%1,%2,%3};"
        : "+f"(c[0]), "+f"(c[1]), "+f"(c[2]), "+f"(c[3])
        : "r"(a[0]), "r"(a[1]), "r"(a[2]), "r"(a[3]), "r"(b[0]), "r"(b[1]));
}
__device__ __forceinline__ void cp16(uint32_t saddr, const void* g) {
    asm volatile("cp.async.cg.shared.global [%0], [%1], 16;"
                 :: "r"(saddr), "l"(g));
}
#define CP_COMMIT() asm volatile("cp.async.commit_group;" ::: "memory")
#define CP_WAIT0()  asm volatile("cp.async.wait_group 0;" ::: "memory")
#define CP_WAIT1()  asm volatile("cp.async.wait_group 1;" ::: "memory")

// ---------------- weight prep: W[k][n] -> B[w][n][k] hi/lo bf16 -------------
__global__ void prep_w_kernel(const float* __restrict__ W0, const float* __restrict__ W1,
                              const float* __restrict__ W2, const float* __restrict__ W3,
                              const float* __restrict__ W4, const float* __restrict__ W5,
                              __nv_bfloat16* __restrict__ bhi,
                              __nv_bfloat16* __restrict__ blo)
{
    int i = blockIdx.x * blockDim.x + threadIdx.x;
    if (i >= 6 * 128 * 256) return;
    int w = i >> 15;
    int rem = i & 32767;
    int nrow = rem >> 8;
    int k = rem & 255;
    const float* W = (w == 0) ? W0 : (w == 1) ? W1 : (w == 2) ? W2
                   : (w == 3) ? W3 : (w == 4) ? W4 : W5;
    float v = W[k * 128 + nrow];
    __nv_bfloat16 h = __float2bfloat16(v);
    __nv_bfloat16 l = __float2bfloat16(v - __bfloat162float(h));
    bhi[i] = h;
    blo[i] = l;
}

// ---------------- HMMA GEMM: cp.async fp32-staged A + cp.async B ------------
#define ASTR 72
#define KCH 64
#define SM_AHI 0
#define SM_ALO 18432
#define SM_STG 36864
#define SM_B   69632
#define GEMM_SMEM 106496

__device__ __forceinline__ void split1(float x, __nv_bfloat16& h, __nv_bfloat16& l) {
    h = __float2bfloat16(x);
    l = __float2bfloat16(x - __bfloat162float(h));
}

struct GemmArgs {
    const float* feat;
    const __nv_bfloat16* Bhi;
    const __nv_bfloat16* Blo;
    const float *b0, *b1, *b2;
    const float *aD1, *aD2, *aS1, *aS2;
    float* o0;
    __half *o1h, *o2h;
    float *sD1, *sD2, *sS1, *sS2;
    int n;
};

__global__ __launch_bounds__(256, 2)
void gemm_mma_kernel(GemmArgs GP, GemmArgs GA)
{
    extern __shared__ __align__(16) char smem[];
    __shared__ float sacc[2][128];
    const uint32_t sbase = smem_u32(smem);

    const GemmArgs& G = blockIdx.z ? GA : GP;
    const int w    = blockIdx.x;
    const int row0 = blockIdx.y * 128;
    const int tid  = threadIdx.x;
    const int warp = tid >> 5;
    const int lane = tid & 31;
    const int n    = G.n;
    const float* feat = G.feat;

    const __nv_bfloat16* Bh = G.Bhi + (size_t)w * 128 * 256;
    const __nv_bfloat16* Bl = G.Blo + (size_t)w * 128 * 256;

    const int m_base = (warp >> 2) * 64;
    const int n_base = (warp & 3) * 32;

    float c[4][4][4];
#pragma unroll
    for (int mt = 0; mt < 4; mt++)
#pragma unroll
        for (int nt = 0; nt < 4; nt++)
#pragma unroll
            for (int r = 0; r < 4; r++) c[mt][nt][r] = 0.f;

    uint32_t aRow[4], bRow4[2];
#pragma unroll
    for (int mt = 0; mt < 4; mt++) {
        int r = m_base + mt * 16 + (lane & 15);
        aRow[mt] = (uint32_t)(r * ASTR * 2) + (((uint32_t)lane >> 4) << 4);
    }
#pragma unroll
    for (int np = 0; np < 2; np++) {
        int r = n_base + np * 16 + (((int)lane >> 4) << 3) + (lane & 7);
        bRow4[np] = (uint32_t)(r * ASTR * 2) + ((((uint32_t)lane >> 3) & 1) << 4);
    }

    if (tid < 256) sacc[tid >> 7][tid & 127] = 0.f;

    const int b_nr  = tid >> 3;
    const int b_c16 = tid & 7;

    auto issue_B = [&](int kc) {
#pragma unroll
        for (int it = 0; it < 4; it++) {
            int nr = b_nr + it * 32;
            uint32_t off = (uint32_t)((nr * ASTR + b_c16 * 8) * 2);
            cp16(sbase + SM_B + off, Bh + (size_t)nr * DIN + kc + b_c16 * 8);
            cp16(sbase + SM_B + 18432 + off, Bl + (size_t)nr * DIN + kc + b_c16 * 8);
        }
        CP_COMMIT();
    };
    auto issue_STG = [&](int kc) {
#pragma unroll
        for (int it = 0; it < 8; it++) {
            int idx = it * 256 + tid;
            int r   = idx >> 4;
            int c4  = idx & 15;
            if (row0 + r < n)
                cp16(sbase + SM_STG + (uint32_t)(r * 256 + c4 * 16),
                     feat + (size_t)(row0 + r) * DIN + kc + c4 * 4);
        }
        CP_COMMIT();
    };
    auto cvt_STG = [&]() {
#pragma unroll
        for (int it = 0; it < 8; it++) {
            int idx = it * 256 + tid;
            int r   = idx >> 4;
            int c4  = idx & 15;
            float4 v = (row0 + r < n)
                ? *(const float4*)(smem + SM_STG + r * 256 + c4 * 16)
                : make_float4(0.f, 0.f, 0.f, 0.f);
            __nv_bfloat16 h0, l0, h1, l1, h2, l2, h3, l3;
            split1(v.x, h0, l0); split1(v.y, h1, l1);
            split1(v.z, h2, l2); split1(v.w, h3, l3);
            __nv_bfloat162 hA = __halves2bfloat162(h0, h1);
            __nv_bfloat162 hB = __halves2bfloat162(h2, h3);
            __nv_bfloat162 lA = __halves2bfloat162(l0, l1);
            __nv_bfloat162 lB = __halves2bfloat162(l2, l3);
            uint32_t off = (uint32_t)((r * ASTR + c4 * 4) * 2);
            *(uint2*)(smem + SM_AHI + off) =
                make_uint2(*(uint32_t*)&hA, *(uint32_t*)&hB);
            *(uint2*)(smem + SM_ALO + off) =
                make_uint2(*(uint32_t*)&lA, *(uint32_t*)&lB);
        }
    };

    // prologue
    issue_STG(0);
    issue_B(0);
    CP_WAIT0();
    __syncthreads();
    cvt_STG();
    issue_STG(KCH);
    __syncthreads();

    // mainloop
#pragma unroll
    for (int cidx = 0; cidx < 4; cidx++) {
#pragma unroll
        for (int ks = 0; ks < 4; ks++) {
            const uint32_t kofs = (uint32_t)(ks * 32);
            uint32_t bh[4][2], bl[4][2];
#pragma unroll
            for (int np = 0; np < 2; np++) {
                uint32_t t4[4];
                ldsm_x4(t4, sbase + SM_B + bRow4[np] + kofs);
                bh[2 * np][0] = t4[0]; bh[2 * np][1] = t4[1];
                bh[2 * np + 1][0] = t4[2]; bh[2 * np + 1][1] = t4[3];
                ldsm_x4(t4, sbase + SM_B + 18432 + bRow4[np] + kofs);
                bl[2 * np][0] = t4[0]; bl[2 * np][1] = t4[1];
                bl[2 * np + 1][0] = t4[2]; bl[2 * np + 1][1] = t4[3];
            }
#pragma unroll
            for (int mt = 0; mt < 4; mt++) {
                uint32_t ah[4], al[4];
                ldsm_x4(ah, sbase + SM_AHI + aRow[mt] + kofs);
                ldsm_x4(al, sbase + SM_ALO + aRow[mt] + kofs);
#pragma unroll
                for (int nt = 0; nt < 4; nt++) {
                    mma_bf16(c[mt][nt], ah, bh[nt]);
                    mma_bf16(c[mt][nt], al, bh[nt]);
                    mma_bf16(c[mt][nt], ah, bl[nt]);
                }
            }
        }
        __syncthreads();
        if (cidx < 3) {
            issue_B((cidx + 1) * KCH);
            CP_WAIT1();
            cvt_STG();
            if (cidx + 2 <= 3) {
                issue_STG((cidx + 2) * KCH);
                CP_WAIT1();
            } else {
                CP_WAIT0();
            }
            __syncthreads();
        }
    }

    // epilogue
    const float* bw = (w == 0) ? G.b0 : (w == 1) ? G.b1 : G.b2;
    const float* aq1 = (w == 0) ? G.aD1 : (w == 1) ? G.aS1 : G.aS2;
    const int lr = lane >> 2;
    const int lc = (lane & 3) * 2;
    float2 bv[4], a1v[4], a2v[4];
#pragma unroll
    for (int nt = 0; nt < 4; nt++) {
        int col = n_base + nt * 8 + lc;
        bv[nt]  = *(const float2*)(bw + col);
        a1v[nt] = *(const float2*)(aq1 + col);
        a2v[nt] = (w == 0) ? *(const float2*)(G.aD2 + col) : make_float2(0.f, 0.f);
    }

#pragma unroll
    for (int mt = 0; mt < 4; mt++) {
        int r1 = row0 + m_base + mt * 16 + lr;
        int r2 = r1 + 8;
        float pa1 = 0.f, pa2 = 0.f, pb1 = 0.f, pb2 = 0.f;
#pragma unroll
        for (int nt = 0; nt < 4; nt++) {
            int col = n_base + nt * 8 + lc;
            float v0 = c[mt][nt][0] + bv[nt].x;
            float v1 = c[mt][nt][1] + bv[nt].y;
            float v2 = c[mt][nt][2] + bv[nt].x;
            float v3 = c[mt][nt][3] + bv[nt].y;
            if (w == 0) {
                if (r1 < n) *(float2*)(G.o0 + (size_t)r1 * DOUT + col) = make_float2(v0, v1);
                if (r2 < n) *(float2*)(G.o0 + (size_t)r2 * DOUT + col) = make_float2(v2, v3);
            } else {
                __half* oh = (w == 1) ? G.o1h : G.o2h;
                if (r1 < n) *(__half2*)(oh + (size_t)r1 * DOUT + col) = __floats2half2_rn(v0, v1);
                if (r2 < n) *(__half2*)(oh + (size_t)r2 * DOUT + col) = __floats2half2_rn(v2, v3);
            }
            pa1 += v0 * a1v[nt].x + v1 * a1v[nt].y;
            pa2 += v2 * a1v[nt].x + v3 * a1v[nt].y;
            if (w == 0) {
                pb1 += v0 * a2v[nt].x + v1 * a2v[nt].y;
                pb2 += v2 * a2v[nt].x + v3 * a2v[nt].y;
            }
        }
        pa1 += __shfl_xor_sync(0xffffffffu, pa1, 1);
        pa1 += __shfl_xor_sync(0xffffffffu, pa1, 2);
        pa2 += __shfl_xor_sync(0xffffffffu, pa2, 1);
        pa2 += __shfl_xor_sync(0xffffffffu, pa2, 2);
        pb1 += __shfl_xor_sync(0xffffffffu, pb1, 1);
        pb1 += __shfl_xor_sync(0xffffffffu, pb1, 2);
        pb2 += __shfl_xor_sync(0xffffffffu, pb2, 1);
        pb2 += __shfl_xor_sync(0xffffffffu, pb2, 2);
        if ((lane & 3) == 0) {
            int lrow = m_base + mt * 16 + lr;
            atomicAdd(&sacc[0][lrow], pa1);
            atomicAdd(&sacc[0][lrow + 8], pa2);
            if (w == 0) {
                atomicAdd(&sacc[1][lrow], pb1);
                atomicAdd(&sacc[1][lrow + 8], pb2);
            }
        }
    }
    __syncthreads();
    if (tid < 128 && row0 + tid < n) {
        if (w == 0) {
            G.sD1[row0 + tid] = sacc[0][tid];
            G.sD2[row0 + tid] = sacc[1][tid];
        } else if (w == 1) {
            G.sS1[row0 + tid] = sacc[0][tid];
        } else {
            G.sS2[row0 + tid] = sacc[0][tid];
        }
    }
}

// ---------------- edge pipeline ---------------------------------------------
struct EdgeParams {
    const int*   src[4];
    const int*   dst[4];
    const float* ssrc[4];
    int2*        bkt[4];
    int*         cnt[4];
};

__global__ void zero_cnt_kernel(int* __restrict__ cnt)
{
    int i = blockIdx.x * blockDim.x + threadIdx.x;
    if (i < 4 * NP) cnt[i] = 0;
}

// Scatter: ONE random load (ssrc[s]); sdst added in gather (broadcast there).
__global__ void scatter4_kernel(EdgeParams P)
{
    const int t = blockIdx.y;
    int i = blockIdx.x * blockDim.x + threadIdx.x;
    if (i >= NE) return;
    int s = P.src[t][i];
    int d = P.dst[t][i];
    float es = __ldg(&P.ssrc[t][s]);
    int pos = atomicAdd(&P.cnt[t][d], 1);
    if (pos < CAP)
        __stcs(&P.bkt[t][(size_t)d * CAP + pos], make_int2(s, __float_as_int(es)));
}

// One type's softmax-weighted gather; weighted loop manually unrolled x4 for MLP.
__device__ __forceinline__ float4 gat_one(const int* __restrict__ cnt,
                                          const int2* __restrict__ bkt,
                                          const __half* __restrict__ msg,
                                          float sd, int node, int lane)
{
    int c = cnt[node];
    if (c > CAP) c = CAP;
    float4 acc = make_float4(0.f, 0.f, 0.f, 0.f);
    if (c == 0) return acc;
    const int2* bp = bkt + (size_t)node * CAP;

    float m = -3.0e38f;
    for (int j = lane; j < c; j += 32) {
        float ev = __int_as_float(bp[j].y) + sd;
        ev = ev > 0.f ? ev : SLOPE * ev;
        m = fmaxf(m, ev);
    }
#pragma unroll
    for (int o = 16; o > 0; o >>= 1)
        m = fmaxf(m, __shfl_xor_sync(0xffffffffu, m, o));

    float dsum = 0.f;
    for (int j = lane; j < c; j += 32) {
        float ev = __int_as_float(bp[j].y) + sd;
        ev = ev > 0.f ? ev : SLOPE * ev;
        dsum += __expf(ev - m);
    }
#pragma unroll
    for (int o = 16; o > 0; o >>= 1)
        dsum += __shfl_xor_sync(0xffffffffu, dsum, o);
    float inv = 1.f / dsum;

    const uint32_t loff = (uint32_t)lane * 4;
    int j = 0;
    // 4x-unrolled weighted sum: 4 independent random msg loads in flight
    for (; j + 4 <= c; j += 4) {
        int2 b0 = bp[j], b1 = bp[j + 1], b2 = bp[j + 2], b3 = bp[j + 3];
        const uint2* p0 = (const uint2*)(msg + (size_t)b0.x * DOUT + loff);
        const uint2* p1 = (const uint2*)(msg + (size_t)b1.x * DOUT + loff);
        const uint2* p2 = (const uint2*)(msg + (size_t)b2.x * DOUT + loff);
        const uint2* p3 = (const uint2*)(msg + (size_t)b3.x * DOUT + loff);
        uint2 r0 = *p0, r1 = *p1, r2 = *p2, r3 = *p3;   // batched loads
        float e0 = __int_as_float(b0.y) + sd; e0 = e0 > 0.f ? e0 : SLOPE * e0;
        float e1 = __int_as_float(b1.y) + sd; e1 = e1 > 0.f ? e1 : SLOPE * e1;
        float e2 = __int_as_float(b2.y) + sd; e2 = e2 > 0.f ? e2 : SLOPE * e2;
        float e3 = __int_as_float(b3.y) + sd; e3 = e3 > 0.f ? e3 : SLOPE * e3;
        float w0 = __expf(e0 - m), w1 = __expf(e1 - m);
        float w2 = __expf(e2 - m), w3 = __expf(e3 - m);
        float2 f;
        f = __half22float2(*(__half2*)&r0.x); acc.x += w0 * f.x; acc.y += w0 * f.y;
        f = __half22float2(*(__half2*)&r0.y); acc.z += w0 * f.x; acc.w += w0 * f.y;
        f = __half22float2(*(__half2*)&r1.x); acc.x += w1 * f.x; acc.y += w1 * f.y;
        f = __half22float2(*(__half2*)&r1.y); acc.z += w1 * f.x; acc.w += w1 * f.y;
        f = __half22float2(*(__half2*)&r2.x); acc.x += w2 * f.x; acc.y += w2 * f.y;
        f = __half22float2(*(__half2*)&r2.y); acc.z += w2 * f.x; acc.w += w2 * f.y;
        f = __half22float2(*(__half2*)&r3.x); acc.x += w3 * f.x; acc.y += w3 * f.y;
        f = __half22float2(*(__half2*)&r3.y); acc.z += w3 * f.x; acc.w += w3 * f.y;
    }
    for (; j < c; j++) {
        int2 b = bp[j];
        float ev = __int_as_float(b.y) + sd;
        ev = ev > 0.f ? ev : SLOPE * ev;
        float w = __expf(ev - m);
        uint2 raw = *(const uint2*)(msg + (size_t)b.x * DOUT + loff);
        float2 f01 = __half22float2(*(__half2*)&raw.x);
        float2 f23 = __half22float2(*(__half2*)&raw.y);
        acc.x += w * f01.x;
        acc.y += w * f01.y;
        acc.z += w * f23.x;
        acc.w += w * f23.y;
    }
    acc.x *= inv; acc.y *= inv; acc.z *= inv; acc.w *= inv;
    return acc;
}

__global__ void gather_combine_kernel(
    const int* __restrict__ cnt0, const int2* __restrict__ bkt0,
    const __half* __restrict__ msg0, const float* __restrict__ sdst0,
    const int* __restrict__ cnt1, const int2* __restrict__ bkt1,
    const __half* __restrict__ msg1, const float* __restrict__ sdst1,
    const float* __restrict__ Wh, float* __restrict__ out, int n)
{
    int node = (blockIdx.x * blockDim.x + threadIdx.x) >> 5;
    int lane = threadIdx.x & 31;
    if (node >= n) return;

    float sd0 = __ldg(&sdst0[node]);
    float sd1 = __ldg(&sdst1[node]);
    float4 r0 = gat_one(cnt0, bkt0, msg0, sd0, node, lane);
    float4 r1 = gat_one(cnt1, bkt1, msg1, sd1, node, lane);
    float4 v  = *(const float4*)(Wh + (size_t)node * DOUT + lane * 4);
    v.x = fmaxf(v.x + r0.x + r1.x, 0.f);
    v.y = fmaxf(v.y + r0.y + r1.y, 0.f);
    v.z = fmaxf(v.z + r0.z + r1.z, 0.f);
    v.w = fmaxf(v.w + r0.w + r1.w, 0.f);
    *(float4*)(out + (size_t)node * DOUT + lane * 4) = v;
}

// ---------------- launch ----------------------------------------------------
static void* sym_addr(const void* sym)
{
    void* p = nullptr;
    cudaGetSymbolAddress(&p, sym);
    return p;
}

extern "C" void kernel_launch(void* const* d_in, const int* in_sizes, int n_in,
                              void* d_out, int out_size)
{
    const float* feat_P  = (const float*)d_in[0];
    const float* feat_A  = (const float*)d_in[1];
    const int*   p2p_src = (const int*)d_in[2];
    const int*   p2p_dst = (const int*)d_in[3];
    const int*   p2a_src = (const int*)d_in[4];
    const int*   p2a_dst = (const int*)d_in[5];
    const int*   a2p_src = (const int*)d_in[6];
    const int*   a2p_dst = (const int*)d_in[7];
    const int*   a2a_src = (const int*)d_in[8];
    const int*   a2a_dst = (const int*)d_in[9];
    const float* W_P   = (const float*)d_in[10];
    const float* b_P   = (const float*)d_in[11];
    const float* W_A   = (const float*)d_in[12];
    const float* b_A   = (const float*)d_in[13];
    const float* W_p2p = (const float*)d_in[14];
    const float* b_p2p = (const float*)d_in[15];
    const float* W_p2a = (const float*)d_in[16];
    const float* b_p2a = (const float*)d_in[17];
    const float* W_a2p = (const float*)d_in[18];
    const float* b_a2p = (const float*)d_in[19];
    const float* W_a2a = (const float*)d_in[20];
    const float* b_a2a = (const float*)d_in[21];
    const float* a_p2p = (const float*)d_in[22];
    const float* a_p2a = (const float*)d_in[23];
    const float* a_a2p = (const float*)d_in[24];
    const float* a_a2a = (const float*)d_in[25];

    float* Wh_P  = (float*)sym_addr(g_Wh_P);
    float* Wh_A  = (float*)sym_addr(g_Wh_A);
    __half* m_p2p = (__half*)sym_addr(g_m_p2p);
    __half* m_p2a = (__half*)sym_addr(g_m_p2a);
    __half* m_a2p = (__half*)sym_addr(g_m_a2p);
    __half* m_a2a = (__half*)sym_addr(g_m_a2a);
    float* s_p2p_src = (float*)sym_addr(g_s_p2p_src);
    float* s_p2p_dst = (float*)sym_addr(g_s_p2p_dst);
    float* s_p2a_src = (float*)sym_addr(g_s_p2a_src);
    float* s_p2a_dst = (float*)sym_addr(g_s_p2a_dst);
    float* s_a2p_src = (float*)sym_addr(g_s_a2p_src);
    float* s_a2p_dst = (float*)sym_addr(g_s_a2p_dst);
    float* s_a2a_src = (float*)sym_addr(g_s_a2a_src);
    float* s_a2a_dst = (float*)sym_addr(g_s_a2a_dst);
    int2* bkt = (int2*)sym_addr(g_bkt);
    int*  cnt = (int*)sym_addr(g_cnt);
    __nv_bfloat16* Bhi = (__nv_bfloat16*)sym_addr(g_Bhi);
    __nv_bfloat16* Blo = (__nv_bfloat16*)sym_addr(g_Blo);

    float* out = (float*)d_out;

    // 0) weight transpose + bf16 split; zero counters
    prep_w_kernel<<<(6 * 128 * 256 + 255) / 256, 256>>>(
        W_P, W_p2p, W_p2a, W_A, W_a2p, W_a2a, Bhi, Blo);
    zero_cnt_kernel<<<(4 * NP + 255) / 256, 256>>>(cnt);

    // 1) merged HMMA GEMM launch (both families; z selects)
    cudaFuncSetAttribute(gemm_mma_kernel,
                         cudaFuncAttributeMaxDynamicSharedMemorySize, GEMM_SMEM);
    {
        GemmArgs GP, GA;
        GP.feat = feat_P; GP.n = NP;
        GP.Bhi = Bhi; GP.Blo = Blo;
        GP.b0 = b_P; GP.b1 = b_p2p; GP.b2 = b_p2a;
        GP.aD1 = a_p2p + DOUT; GP.aD2 = a_a2p + DOUT;
        GP.aS1 = a_p2p; GP.aS2 = a_p2a;
        GP.o0 = Wh_P; GP.o1h = m_p2p; GP.o2h = m_p2a;
        GP.sD1 = s_p2p_dst; GP.sD2 = s_a2p_dst;
        GP.sS1 = s_p2p_src; GP.sS2 = s_p2a_src;

        GA.feat = feat_A; GA.n = NA;
        GA.Bhi = Bhi + 3 * 128 * 256; GA.Blo = Blo + 3 * 128 * 256;
        GA.b0 = b_A; GA.b1 = b_a2p; GA.b2 = b_a2a;
        GA.aD1 = a_p2a + DOUT; GA.aD2 = a_a2a + DOUT;
        GA.aS1 = a_a2p; GA.aS2 = a_a2a;
        GA.o0 = Wh_A; GA.o1h = m_a2p; GA.o2h = m_a2a;
        GA.sD1 = s_p2a_dst; GA.sD2 = s_a2a_dst;
        GA.sS1 = s_a2p_src; GA.sS2 = s_a2a_src;

        dim3 grid(3, (NP + 127) / 128, 2);
        gemm_mma_kernel<<<grid, 256, GEMM_SMEM>>>(GP, GA);
    }

    // 2) scatter (4 types in one launch; one random load per edge)
    EdgeParams EP;
    EP.src[0] = p2p_src; EP.dst[0] = p2p_dst; EP.ssrc[0] = s_p2p_src;
    EP.src[1] = a2p_src; EP.dst[1] = a2p_dst; EP.ssrc[1] = s_a2p_src;
    EP.src[2] = p2a_src; EP.dst[2] = p2a_dst; EP.ssrc[2] = s_p2a_src;
    EP.src[3] = a2a_src; EP.dst[3] = a2a_dst; EP.ssrc[3] = s_a2a_src;
    for (int t = 0; t < 4; t++) {
        EP.bkt[t] = bkt + (size_t)t * NP * CAP;
        EP.cnt[t] = cnt + (size_t)t * NP;
    }
    {
        dim3 gs((NE + 255) / 256, 4);
        scatter4_kernel<<<gs, 256>>>(EP);
    }

    // 3) fused gather + combine + ReLU -> final output
    {
        int grid = (NP * 32 + 255) / 256;
        gather_combine_kernel<<<grid, 256>>>(
            EP.cnt[0], EP.bkt[0], m_p2p, s_p2p_dst,
            EP.cnt[1], EP.bkt[1], m_a2p, s_a2p_dst,
            Wh_P, out, NP);
        gather_combine_kernel<<<grid, 256>>>(
            EP.cnt[2], EP.bkt[2], m_p2a, s_p2a_dst,
            EP.cnt[3], EP.bkt[3], m_a2a, s_a2a_dst,
            Wh_A, out + (size_t)NP * DOUT, NA);
    }
}